// round 14
// baseline (speedup 1.0000x reference)
#include <cuda_runtime.h>
#include <cuda_bf16.h>
#include <math.h>
#include <stdint.h>

#define NN 50000
#define D 256
#define NE 800000
#define PAD 64
#define SPILL_MAX 8192

// ---------------------------------------------------------------------------
// Scratch (allocation-free rule: __device__ globals)
// ---------------------------------------------------------------------------
__device__ __nv_bfloat16 g_ah[(size_t)NN * D];
__device__ __nv_bfloat16 g_al[(size_t)NN * D];
__device__ __nv_bfloat16 g_ch[(size_t)NN * D];
__device__ __nv_bfloat16 g_cl[(size_t)NN * D];
__device__ float g_x[(size_t)NN * D];
__device__ int   g_cnt[NN];
__device__ int2  g_esw[(size_t)NN * PAD];
__device__ int4  g_spill[SPILL_MAX];
__device__ int   g_spill_cnt;
__device__ uint4 g_bp1[16 * 32 * 32];
__device__ uint4 g_bp2[16 * 32 * 32];
__device__ uint4 g_bp3[16 * 32 * 32];

__device__ __forceinline__ uint32_t pk(__nv_bfloat16 a, __nv_bfloat16 b) {
    return (uint32_t)__bfloat16_as_ushort(a) | ((uint32_t)__bfloat16_as_ushort(b) << 16);
}

// ---------------------------------------------------------------------------
// Bucket build (one pass)
// ---------------------------------------------------------------------------
__global__ void bucket_kernel(const int* __restrict__ src, const int* __restrict__ dst,
                              const float* __restrict__ ew, int* __restrict__ cnt,
                              int2* __restrict__ esw, int4* __restrict__ spill,
                              int* __restrict__ spill_cnt, int ne) {
    int e = blockIdx.x * blockDim.x + threadIdx.x;
    if (e >= ne) return;
    int d = dst[e];
    int s = src[e];
    int wb = __float_as_int(ew[e]);
    int pos = atomicAdd(cnt + d, 1);
    if (pos < PAD) {
        esw[(size_t)d * PAD + pos] = make_int2(s, wb);
    } else {
        int sp = atomicAdd(spill_cnt, 1);
        if (sp < SPILL_MAX) spill[sp] = make_int4(s, d, wb, 0);
    }
}

// ---------------------------------------------------------------------------
// Weight prep (all three matrices, grid.y selects matrix).
// ---------------------------------------------------------------------------
__global__ void prep_b_kernel(const float* __restrict__ Wa, const float* __restrict__ Wb,
                              const float* __restrict__ Wc, uint4* __restrict__ pa,
                              uint4* __restrict__ pb, uint4* __restrict__ pc) {
    const float* W = (blockIdx.y == 0) ? Wa : (blockIdx.y == 1) ? Wb : Wc;
    uint4* bp = (blockIdx.y == 0) ? pa : (blockIdx.y == 1) ? pb : pc;
    int idx = blockIdx.x * 256 + threadIdx.x;
    if (idx >= 16 * 32 * 32) return;
    int lane = idx & 31, ntg = (idx >> 5) & 31, kt = idx >> 10;
    int t = lane & 3, g = lane >> 2;
    int nn = ntg * 8 + g;
    int k0 = kt * 16 + 2 * t;
    float w0 = W[(size_t)k0 * D + nn];
    float w1 = W[(size_t)(k0 + 1) * D + nn];
    float w2 = W[(size_t)(k0 + 8) * D + nn];
    float w3 = W[(size_t)(k0 + 9) * D + nn];
    __nv_bfloat16 h0 = __float2bfloat16_rn(w0), h1 = __float2bfloat16_rn(w1);
    __nv_bfloat16 h2 = __float2bfloat16_rn(w2), h3 = __float2bfloat16_rn(w3);
    __nv_bfloat16 l0 = __float2bfloat16_rn(w0 - __bfloat162float(h0));
    __nv_bfloat16 l1 = __float2bfloat16_rn(w1 - __bfloat162float(h1));
    __nv_bfloat16 l2 = __float2bfloat16_rn(w2 - __bfloat162float(h2));
    __nv_bfloat16 l3 = __float2bfloat16_rn(w3 - __bfloat162float(h3));
    uint4 v;
    v.x = pk(h0, h1); v.y = pk(h2, h3);
    v.z = pk(l0, l1); v.w = pk(l2, l3);
    bp[idx] = v;
}

// ---------------------------------------------------------------------------
// split fp32x4 -> hi/lo bf16 planes
// ---------------------------------------------------------------------------
__device__ __forceinline__ void wr_split(__nv_bfloat16* Hp, __nv_bfloat16* Lp, float4 a) {
    __nv_bfloat16 h0 = __float2bfloat16_rn(a.x), h1 = __float2bfloat16_rn(a.y);
    __nv_bfloat16 h2 = __float2bfloat16_rn(a.z), h3 = __float2bfloat16_rn(a.w);
    __nv_bfloat16 l0 = __float2bfloat16_rn(a.x - __bfloat162float(h0));
    __nv_bfloat16 l1 = __float2bfloat16_rn(a.y - __bfloat162float(h1));
    __nv_bfloat16 l2 = __float2bfloat16_rn(a.z - __bfloat162float(h2));
    __nv_bfloat16 l3 = __float2bfloat16_rn(a.w - __bfloat162float(h3));
    uint2 uh, ul;
    uh.x = pk(h0, h1); uh.y = pk(h2, h3);
    ul.x = pk(l0, l1); ul.y = pk(l2, l3);
    *reinterpret_cast<uint2*>(Hp) = uh;
    *reinterpret_cast<uint2*>(Lp) = ul;
}

// ---------------------------------------------------------------------------
// SPMM + residual -> bf16 hi/lo planes for node range [n0, n1).
// ---------------------------------------------------------------------------
__global__ void __launch_bounds__(256)
spmm_kernel(const float* __restrict__ x, const int2* __restrict__ esw,
            const int* __restrict__ cnt, const int4* __restrict__ spill,
            const int* __restrict__ spill_cnt,
            __nv_bfloat16* __restrict__ Ah, __nv_bfloat16* __restrict__ Al,
            int n0, int n1) {
    int node = n0 + ((blockIdx.x * blockDim.x + threadIdx.x) >> 5);
    if (node >= n1) return;
    int lane = threadIdx.x & 31;

    const float4* xr = reinterpret_cast<const float4*>(x + (size_t)node * D);
    float4 acc0 = xr[lane];
    float4 acc1 = xr[lane + 32];

    int mraw = cnt[node];
    int m = mraw < PAD ? mraw : PAD;
    const int2* bp = esw + (size_t)node * PAD;
    for (int j = 0; j < m; j++) {
        int2 p = __ldg(bp + j);
        float w = __int_as_float(p.y);
        const float4* sr = reinterpret_cast<const float4*>(x + (size_t)p.x * D);
        float4 a = sr[lane];
        float4 b = sr[lane + 32];
        acc0.x = fmaf(w, a.x, acc0.x); acc0.y = fmaf(w, a.y, acc0.y);
        acc0.z = fmaf(w, a.z, acc0.z); acc0.w = fmaf(w, a.w, acc0.w);
        acc1.x = fmaf(w, b.x, acc1.x); acc1.y = fmaf(w, b.y, acc1.y);
        acc1.z = fmaf(w, b.z, acc1.z); acc1.w = fmaf(w, b.w, acc1.w);
    }
    if (mraw > PAD) {  // deterministic spill scan (expected count 0)
        int sc = *spill_cnt;
        if (sc > SPILL_MAX) sc = SPILL_MAX;
        for (int j = 0; j < sc; j++) {
            int4 e = spill[j];
            if (e.y != node) continue;
            float w = __int_as_float(e.z);
            const float4* sr = reinterpret_cast<const float4*>(x + (size_t)e.x * D);
            float4 a = sr[lane];
            float4 b = sr[lane + 32];
            acc0.x = fmaf(w, a.x, acc0.x); acc0.y = fmaf(w, a.y, acc0.y);
            acc0.z = fmaf(w, a.z, acc0.z); acc0.w = fmaf(w, a.w, acc0.w);
            acc1.x = fmaf(w, b.x, acc1.x); acc1.y = fmaf(w, b.y, acc1.y);
            acc1.z = fmaf(w, b.z, acc1.z); acc1.w = fmaf(w, b.w, acc1.w);
        }
    }
    size_t base = (size_t)node * D + lane * 4;
    wr_split(Ah + base, Al + base, acc0);
    wr_split(Ah + base + 128, Al + base + 128, acc1);
}

// ---------------------------------------------------------------------------
// Split-bf16 tensor-core GEMM + fused epilogue (R6-proven mainloop).
// mbase: row offset of this launch's first tile.
// MODE 0: LN+GELU -> fp32 x. MODE 1: LN+GELU -> bf16 planes. MODE 2: +bias -> fp32.
// ---------------------------------------------------------------------------
#define APITCH 264
#define ASMEM_ELEMS (64 * APITCH)
#define ASMEM_BYTES (2 * ASMEM_ELEMS * 2)

#define MMA_BF16(c, a, b0, b1)                                                        \
    asm volatile(                                                                     \
        "mma.sync.aligned.m16n8k16.row.col.f32.bf16.bf16.f32 "                        \
        "{%0,%1,%2,%3}, {%4,%5,%6,%7}, {%8,%9}, {%0,%1,%2,%3};"                       \
        : "+f"(c[0]), "+f"(c[1]), "+f"(c[2]), "+f"(c[3])                              \
        : "r"(a[0]), "r"(a[1]), "r"(a[2]), "r"(a[3]), "r"(b0), "r"(b1))

template<int MODE>
__global__ void __launch_bounds__(256, 2)
hgemm_kernel(const __nv_bfloat16* __restrict__ Ah, const __nv_bfloat16* __restrict__ Al,
             const uint4* __restrict__ Bp, const float* __restrict__ bias,
             const float* __restrict__ gamma, const float* __restrict__ beta,
             float* __restrict__ xout, __nv_bfloat16* __restrict__ oh,
             __nv_bfloat16* __restrict__ ol, float* __restrict__ fout,
             int mbase, int n) {
    extern __shared__ __nv_bfloat16 sA[];
    __shared__ float red[64][4][2];

    int tid = threadIdx.x, lane = tid & 31, w = tid >> 5;
    int wn = w & 3, wm = w >> 2;
    int t = lane & 3, g = lane >> 2;
    int m0 = mbase + blockIdx.x * 64;
    int rbase = m0 + wm * 32 + g;

    {
        __nv_bfloat16* sAh = sA;
        __nv_bfloat16* sAl = sA + ASMEM_ELEMS;
#pragma unroll
        for (int i = 0; i < 16; i++) {
            int idx = tid + 256 * i;
            int plane = idx >> 11;
            int j = idx & 2047;
            int r = j >> 5, q = j & 31;
            int gr = m0 + r;
            uint4 v = make_uint4(0u, 0u, 0u, 0u);
            const __nv_bfloat16* sp = plane ? Al : Ah;
            if (gr < n) v = *reinterpret_cast<const uint4*>(sp + (size_t)gr * D + q * 8);
            __nv_bfloat16* dp = plane ? sAl : sAh;
            *reinterpret_cast<uint4*>(dp + r * APITCH + q * 8) = v;
        }
    }
    __syncthreads();

    const uint32_t* sh32 = reinterpret_cast<const uint32_t*>(sA);
    const uint32_t* sl32 = reinterpret_cast<const uint32_t*>(sA) + ASMEM_ELEMS / 2;
    int arow = wm * 32 + g;

    float acc[2][8][4];
#pragma unroll
    for (int mt = 0; mt < 2; mt++)
#pragma unroll
        for (int nt = 0; nt < 8; nt++)
#pragma unroll
            for (int c = 0; c < 4; c++) acc[mt][nt][c] = 0.f;

    const uint4* bwarp = Bp + (size_t)(wn * 8) * 32 + lane;

#pragma unroll
    for (int kt = 0; kt < 16; kt++) {
        int ko = kt * 8 + t;
        uint32_t ah[2][4], al[2][4];
#pragma unroll
        for (int mt = 0; mt < 2; mt++) {
            int r0 = (arow + mt * 16) * 132;
            int r1 = r0 + 8 * 132;
            ah[mt][0] = sh32[r0 + ko];
            ah[mt][1] = sh32[r1 + ko];
            ah[mt][2] = sh32[r0 + ko + 4];
            ah[mt][3] = sh32[r1 + ko + 4];
            al[mt][0] = sl32[r0 + ko];
            al[mt][1] = sl32[r1 + ko];
            al[mt][2] = sl32[r0 + ko + 4];
            al[mt][3] = sl32[r1 + ko + 4];
        }
        const uint4* bk = bwarp + (size_t)(kt * 32) * 32;
        uint4 bcur = __ldg(bk);
#pragma unroll
        for (int nt = 0; nt < 8; nt++) {
            uint4 bnext = (nt < 7) ? __ldg(bk + (size_t)(nt + 1) * 32) : bcur;
#pragma unroll
            for (int mt = 0; mt < 2; mt++) {
                MMA_BF16(acc[mt][nt], ah[mt], bcur.x, bcur.y);
                MMA_BF16(acc[mt][nt], ah[mt], bcur.z, bcur.w);
                MMA_BF16(acc[mt][nt], al[mt], bcur.x, bcur.y);
            }
            bcur = bnext;
        }
    }

    if (MODE == 2) {
#pragma unroll
        for (int mt = 0; mt < 2; mt++)
#pragma unroll
            for (int half = 0; half < 2; half++) {
                int row = rbase + mt * 16 + half * 8;
                if (row >= n) continue;
#pragma unroll
                for (int nt = 0; nt < 8; nt++) {
                    int cb = wn * 64 + nt * 8 + 2 * t;
                    float2 bb = __ldg(reinterpret_cast<const float2*>(bias + cb));
                    float2 o;
                    o.x = acc[mt][nt][half * 2 + 0] + bb.x;
                    o.y = acc[mt][nt][half * 2 + 1] + bb.y;
                    *reinterpret_cast<float2*>(fout + (size_t)row * D + cb) = o;
                }
            }
        return;
    }

    float sm[4] = {0.f, 0.f, 0.f, 0.f}, sq[4] = {0.f, 0.f, 0.f, 0.f};
#pragma unroll
    for (int mt = 0; mt < 2; mt++)
#pragma unroll
        for (int nt = 0; nt < 8; nt++) {
            int cb = wn * 64 + nt * 8 + 2 * t;
            float2 bb = __ldg(reinterpret_cast<const float2*>(bias + cb));
            float v00 = acc[mt][nt][0] + bb.x, v01 = acc[mt][nt][1] + bb.y;
            float v10 = acc[mt][nt][2] + bb.x, v11 = acc[mt][nt][3] + bb.y;
            sm[mt * 2 + 0] += v00 + v01; sq[mt * 2 + 0] += v00 * v00 + v01 * v01;
            sm[mt * 2 + 1] += v10 + v11; sq[mt * 2 + 1] += v10 * v10 + v11 * v11;
        }
#pragma unroll
    for (int r = 0; r < 4; r++) {
#pragma unroll
        for (int o = 1; o < 4; o <<= 1) {
            sm[r] += __shfl_xor_sync(0xffffffffu, sm[r], o);
            sq[r] += __shfl_xor_sync(0xffffffffu, sq[r], o);
        }
    }
    if (t == 0) {
#pragma unroll
        for (int r = 0; r < 4; r++) {
            int lr = wm * 32 + (r >> 1) * 16 + (r & 1) * 8 + g;
            red[lr][wn][0] = sm[r];
            red[lr][wn][1] = sq[r];
        }
    }
    __syncthreads();
    float mean[4], rstd[4];
#pragma unroll
    for (int r = 0; r < 4; r++) {
        int lr = wm * 32 + (r >> 1) * 16 + (r & 1) * 8 + g;
        float S = 0.f, Q = 0.f;
#pragma unroll
        for (int j = 0; j < 4; j++) { S += red[lr][j][0]; Q += red[lr][j][1]; }
        float mu = S * (1.f / 256.f);
        mean[r] = mu;
        rstd[r] = rsqrtf(Q * (1.f / 256.f) - mu * mu + 1e-5f);
    }
#pragma unroll
    for (int mt = 0; mt < 2; mt++)
#pragma unroll
        for (int nt = 0; nt < 8; nt++) {
            int cb = wn * 64 + nt * 8 + 2 * t;
            float2 bb = __ldg(reinterpret_cast<const float2*>(bias + cb));
            float2 gg = __ldg(reinterpret_cast<const float2*>(gamma + cb));
            float2 be = __ldg(reinterpret_cast<const float2*>(beta + cb));
#pragma unroll
            for (int half = 0; half < 2; half++) {
                int row = rbase + mt * 16 + half * 8;
                if (row >= n) continue;
                int r = mt * 2 + half;
                float v0 = acc[mt][nt][half * 2 + 0] + bb.x;
                float v1 = acc[mt][nt][half * 2 + 1] + bb.y;
                float t0 = (v0 - mean[r]) * rstd[r] * gg.x + be.x;
                float t1 = (v1 - mean[r]) * rstd[r] * gg.y + be.y;
                float ge0 = 0.5f * t0 * (1.f + erff(t0 * 0.70710678118654752f));
                float ge1 = 0.5f * t1 * (1.f + erff(t1 * 0.70710678118654752f));
                if (MODE == 0) {
                    float2 o; o.x = ge0; o.y = ge1;
                    *reinterpret_cast<float2*>(xout + (size_t)row * D + cb) = o;
                } else {
                    __nv_bfloat16 h0 = __float2bfloat16_rn(ge0);
                    __nv_bfloat16 h1 = __float2bfloat16_rn(ge1);
                    __nv_bfloat16 l0 = __float2bfloat16_rn(ge0 - __bfloat162float(h0));
                    __nv_bfloat16 l1 = __float2bfloat16_rn(ge1 - __bfloat162float(h1));
                    *reinterpret_cast<uint32_t*>(oh + (size_t)row * D + cb) = pk(h0, h1);
                    *reinterpret_cast<uint32_t*>(ol + (size_t)row * D + cb) = pk(l0, l1);
                }
            }
        }
}

// ---------------------------------------------------------------------------
// launch: two-stream overlapped schedule.
//   s0: bucket -> spmm1.A -> spmm1.B -> gemm1.B -> spmm2.A -> spmm2.B -> gemm2.B -> proj.B
//   s2: prep   ->           gemm1.A             ->           gemm2.A -> proj.A
// GEMM tiles read only their own rows, so row-half dependencies are exact.
// ---------------------------------------------------------------------------
extern "C" void kernel_launch(void* const* d_in, const int* in_sizes, int n_in,
                              void* d_out, int out_size) {
    const float* node = (const float*)d_in[0];
    const int*   src  = (const int*)d_in[1];
    const int*   dst  = (const int*)d_in[2];
    const float* ew   = (const float*)d_in[3];
    const float* W1   = (const float*)d_in[4];
    const float* b1   = (const float*)d_in[5];
    const float* g1   = (const float*)d_in[6];
    const float* be1  = (const float*)d_in[7];
    const float* W2   = (const float*)d_in[8];
    const float* b2   = (const float*)d_in[9];
    const float* g2   = (const float*)d_in[10];
    const float* be2  = (const float*)d_in[11];
    const float* Wp   = (const float*)d_in[12];
    const float* bp   = (const float*)d_in[13];
    float* out = (float*)d_out;

    int n = in_sizes[0] / D;
    int nedges = in_sizes[1];

    __nv_bfloat16 *ah, *al, *ch, *cl;
    float* x;
    int *cnt, *spill_cnt;
    int2* esw;
    int4* spill;
    uint4 *bp1, *bp2, *bp3;
    cudaGetSymbolAddress((void**)&ah, g_ah);
    cudaGetSymbolAddress((void**)&al, g_al);
    cudaGetSymbolAddress((void**)&ch, g_ch);
    cudaGetSymbolAddress((void**)&cl, g_cl);
    cudaGetSymbolAddress((void**)&x, g_x);
    cudaGetSymbolAddress((void**)&cnt, g_cnt);
    cudaGetSymbolAddress((void**)&esw, g_esw);
    cudaGetSymbolAddress((void**)&spill, g_spill);
    cudaGetSymbolAddress((void**)&spill_cnt, g_spill_cnt);
    cudaGetSymbolAddress((void**)&bp1, g_bp1);
    cudaGetSymbolAddress((void**)&bp2, g_bp2);
    cudaGetSymbolAddress((void**)&bp3, g_bp3);

    static cudaStream_t s2 = nullptr;
    static cudaEvent_t eFork = nullptr, ePrep = nullptr, eS1A = nullptr,
                       eG1A = nullptr, eS2A = nullptr, ePA = nullptr;
    static bool inited = false;
    if (!inited) {
        cudaStreamCreateWithFlags(&s2, cudaStreamNonBlocking);
        cudaEventCreateWithFlags(&eFork, cudaEventDisableTiming);
        cudaEventCreateWithFlags(&ePrep, cudaEventDisableTiming);
        cudaEventCreateWithFlags(&eS1A, cudaEventDisableTiming);
        cudaEventCreateWithFlags(&eG1A, cudaEventDisableTiming);
        cudaEventCreateWithFlags(&eS2A, cudaEventDisableTiming);
        cudaEventCreateWithFlags(&ePA, cudaEventDisableTiming);
        cudaFuncSetAttribute(hgemm_kernel<0>, cudaFuncAttributeMaxDynamicSharedMemorySize, ASMEM_BYTES);
        cudaFuncSetAttribute(hgemm_kernel<1>, cudaFuncAttributeMaxDynamicSharedMemorySize, ASMEM_BYTES);
        cudaFuncSetAttribute(hgemm_kernel<2>, cudaFuncAttributeMaxDynamicSharedMemorySize, ASMEM_BYTES);
        inited = true;
    }

    int totTiles = (n + 63) / 64;                 // 782
    int tilesA = totTiles / 2;                    // 391
    int tilesB = totTiles - tilesA;               // 391
    int h = tilesA * 64;                          // 25024 (row split, tile-aligned)
    int edgeBlocks = (nedges + 255) / 256;
    int spmmA = (h + 7) / 8;
    int spmmB = (n - h + 7) / 8;
    dim3 prepGrid((16 * 32 * 32 + 255) / 256, 3);

    // ---- fork s2; prep runs concurrent with bucket build ----
    cudaEventRecord(eFork, 0);
    cudaStreamWaitEvent(s2, eFork, 0);
    prep_b_kernel<<<prepGrid, 256, 0, s2>>>(W1, W2, Wp, bp1, bp2, bp3);
    cudaEventRecord(ePrep, s2);

    cudaMemsetAsync(cnt, 0, (size_t)n * sizeof(int));
    cudaMemsetAsync(spill_cnt, 0, sizeof(int));
    bucket_kernel<<<edgeBlocks, 256>>>(src, dst, ew, cnt, esw, spill, spill_cnt, nedges);

    // ---- Layer 1 ----
    spmm_kernel<<<spmmA, 256>>>(node, esw, cnt, spill, spill_cnt, ah, al, 0, h);
    cudaEventRecord(eS1A, 0);
    cudaStreamWaitEvent(s2, eS1A, 0);
    hgemm_kernel<0><<<tilesA, 256, ASMEM_BYTES, s2>>>(ah, al, bp1, b1, g1, be1,
                                                      x, nullptr, nullptr, nullptr, 0, n);
    cudaEventRecord(eG1A, s2);

    spmm_kernel<<<spmmB, 256>>>(node, esw, cnt, spill, spill_cnt, ah, al, h, n);
    cudaStreamWaitEvent(0, ePrep, 0);
    hgemm_kernel<0><<<tilesB, 256, ASMEM_BYTES>>>(ah, al, bp1, b1, g1, be1,
                                                  x, nullptr, nullptr, nullptr, h, n);

    // ---- Layer 2 ----
    cudaStreamWaitEvent(0, eG1A, 0);               // x complete (A half from s2)
    spmm_kernel<<<spmmA, 256>>>(x, esw, cnt, spill, spill_cnt, ah, al, 0, h);
    cudaEventRecord(eS2A, 0);
    cudaStreamWaitEvent(s2, eS2A, 0);
    hgemm_kernel<1><<<tilesA, 256, ASMEM_BYTES, s2>>>(ah, al, bp2, b2, g2, be2,
                                                      nullptr, ch, cl, nullptr, 0, n);
    hgemm_kernel<2><<<tilesA, 256, ASMEM_BYTES, s2>>>(ch, cl, bp3, bp, nullptr, nullptr,
                                                      nullptr, nullptr, nullptr, out, 0, n);
    cudaEventRecord(ePA, s2);

    spmm_kernel<<<spmmB, 256>>>(x, esw, cnt, spill, spill_cnt, ah, al, h, n);
    hgemm_kernel<1><<<tilesB, 256, ASMEM_BYTES>>>(ah, al, bp2, b2, g2, be2,
                                                  nullptr, ch, cl, nullptr, h, n);
    hgemm_kernel<2><<<tilesB, 256, ASMEM_BYTES>>>(ch, cl, bp3, bp, nullptr, nullptr,
                                                  nullptr, nullptr, nullptr, out, h, n);

    // ---- join ----
    cudaStreamWaitEvent(0, ePA, 0);
}

// round 15
// speedup vs baseline: 1.2787x; 1.2787x over previous
#include <cuda_runtime.h>
#include <cuda_fp16.h>
#include <math.h>
#include <stdint.h>

#define NN 50000
#define D 256
#define NE 800000
#define PAD 64
#define SPILL_MAX 8192

// ---------------------------------------------------------------------------
// Scratch (allocation-free rule: __device__ globals)
// ---------------------------------------------------------------------------
__device__ __half g_ah[(size_t)NN * D];          // activation fp16 plane (layer in)
__device__ __half g_ch[(size_t)NN * D];          // layer-2 output fp16 plane
__device__ float g_x[(size_t)NN * D];            // fp32 layer-1 output (SPMM2 input)
__device__ int   g_cnt[NN];
__device__ int2  g_esw[(size_t)NN * PAD];
__device__ int4  g_spill[SPILL_MAX];
__device__ int   g_spill_cnt;
__device__ uint4 g_bp1[16 * 32 * 32];            // fragment-packed weights fp16 hi|lo
__device__ uint4 g_bp2[16 * 32 * 32];
__device__ uint4 g_bp3[16 * 32 * 32];

__device__ __forceinline__ uint32_t pkh(__half a, __half b) {
    return (uint32_t)__half_as_ushort(a) | ((uint32_t)__half_as_ushort(b) << 16);
}

// ---------------------------------------------------------------------------
// Bucket build (one pass)
// ---------------------------------------------------------------------------
__global__ void bucket_kernel(const int* __restrict__ src, const int* __restrict__ dst,
                              const float* __restrict__ ew, int* __restrict__ cnt,
                              int2* __restrict__ esw, int4* __restrict__ spill,
                              int* __restrict__ spill_cnt, int ne) {
    int e = blockIdx.x * blockDim.x + threadIdx.x;
    if (e >= ne) return;
    int d = dst[e];
    int s = src[e];
    int wb = __float_as_int(ew[e]);
    int pos = atomicAdd(cnt + d, 1);
    if (pos < PAD) {
        esw[(size_t)d * PAD + pos] = make_int2(s, wb);
    } else {
        int sp = atomicAdd(spill_cnt, 1);
        if (sp < SPILL_MAX) spill[sp] = make_int4(s, d, wb, 0);
    }
}

// ---------------------------------------------------------------------------
// Weight prep: fp16 split B = Bh + Bl (exact to ~2^-22).
// idx = (kt*32 + ntile)*32 + lane ; lane: t=lane&3 (k-pair), g=lane>>2 (n).
// uint4 = { Bh(k=2t,2t+1), Bh(k=2t+8,2t+9), Bl(k=2t,2t+1), Bl(k=2t+8,2t+9) }
// ---------------------------------------------------------------------------
__global__ void prep_b_kernel(const float* __restrict__ Wa, const float* __restrict__ Wb,
                              const float* __restrict__ Wc, uint4* __restrict__ pa,
                              uint4* __restrict__ pb, uint4* __restrict__ pc) {
    const float* W = (blockIdx.y == 0) ? Wa : (blockIdx.y == 1) ? Wb : Wc;
    uint4* bp = (blockIdx.y == 0) ? pa : (blockIdx.y == 1) ? pb : pc;
    int idx = blockIdx.x * 256 + threadIdx.x;
    if (idx >= 16 * 32 * 32) return;
    int lane = idx & 31, ntg = (idx >> 5) & 31, kt = idx >> 10;
    int t = lane & 3, g = lane >> 2;
    int nn = ntg * 8 + g;
    int k0 = kt * 16 + 2 * t;
    float w0 = W[(size_t)k0 * D + nn];
    float w1 = W[(size_t)(k0 + 1) * D + nn];
    float w2 = W[(size_t)(k0 + 8) * D + nn];
    float w3 = W[(size_t)(k0 + 9) * D + nn];
    __half h0 = __float2half_rn(w0), h1 = __float2half_rn(w1);
    __half h2 = __float2half_rn(w2), h3 = __float2half_rn(w3);
    __half l0 = __float2half_rn(w0 - __half2float(h0));
    __half l1 = __float2half_rn(w1 - __half2float(h1));
    __half l2 = __float2half_rn(w2 - __half2float(h2));
    __half l3 = __float2half_rn(w3 - __half2float(h3));
    uint4 v;
    v.x = pkh(h0, h1); v.y = pkh(h2, h3);
    v.z = pkh(l0, l1); v.w = pkh(l2, l3);
    bp[idx] = v;
}

// ---------------------------------------------------------------------------
// fp32x4 -> fp16x4 packed (uint2)
// ---------------------------------------------------------------------------
__device__ __forceinline__ void wr_half(__half* Hp, float4 a) {
    uint2 u;
    u.x = pkh(__float2half_rn(a.x), __float2half_rn(a.y));
    u.y = pkh(__float2half_rn(a.z), __float2half_rn(a.w));
    *reinterpret_cast<uint2*>(Hp) = u;
}

// ---------------------------------------------------------------------------
// SPMM + residual -> fp16 plane. One warp per node, no atomics (fp32 gather).
// ---------------------------------------------------------------------------
__global__ void __launch_bounds__(256)
spmm_kernel(const float* __restrict__ x, const int2* __restrict__ esw,
            const int* __restrict__ cnt, const int4* __restrict__ spill,
            const int* __restrict__ spill_cnt,
            __half* __restrict__ Ah, int n) {
    int node = (blockIdx.x * blockDim.x + threadIdx.x) >> 5;
    if (node >= n) return;
    int lane = threadIdx.x & 31;

    const float4* xr = reinterpret_cast<const float4*>(x + (size_t)node * D);
    float4 acc0 = xr[lane];
    float4 acc1 = xr[lane + 32];

    int mraw = cnt[node];
    int m = mraw < PAD ? mraw : PAD;
    const int2* bp = esw + (size_t)node * PAD;
    for (int j = 0; j < m; j++) {
        int2 p = __ldg(bp + j);
        float w = __int_as_float(p.y);
        const float4* sr = reinterpret_cast<const float4*>(x + (size_t)p.x * D);
        float4 a = sr[lane];
        float4 b = sr[lane + 32];
        acc0.x = fmaf(w, a.x, acc0.x); acc0.y = fmaf(w, a.y, acc0.y);
        acc0.z = fmaf(w, a.z, acc0.z); acc0.w = fmaf(w, a.w, acc0.w);
        acc1.x = fmaf(w, b.x, acc1.x); acc1.y = fmaf(w, b.y, acc1.y);
        acc1.z = fmaf(w, b.z, acc1.z); acc1.w = fmaf(w, b.w, acc1.w);
    }
    if (mraw > PAD) {  // deterministic spill scan (expected count 0)
        int sc = *spill_cnt;
        if (sc > SPILL_MAX) sc = SPILL_MAX;
        for (int j = 0; j < sc; j++) {
            int4 e = spill[j];
            if (e.y != node) continue;
            float w = __int_as_float(e.z);
            const float4* sr = reinterpret_cast<const float4*>(x + (size_t)e.x * D);
            float4 a = sr[lane];
            float4 b = sr[lane + 32];
            acc0.x = fmaf(w, a.x, acc0.x); acc0.y = fmaf(w, a.y, acc0.y);
            acc0.z = fmaf(w, a.z, acc0.z); acc0.w = fmaf(w, a.w, acc0.w);
            acc1.x = fmaf(w, b.x, acc1.x); acc1.y = fmaf(w, b.y, acc1.y);
            acc1.z = fmaf(w, b.z, acc1.z); acc1.w = fmaf(w, b.w, acc1.w);
        }
    }
    size_t base = (size_t)node * D + lane * 4;
    wr_half(Ah + base, acc0);
    wr_half(Ah + base + 128, acc1);
}

// ---------------------------------------------------------------------------
// fp16 2-term tensor-core GEMM + fused epilogue.
// Block 64(m) x 256(n), 8 warps (2m x 4n), warp tile 32x64, mma.m16n8k16.f16.
// D = A16 * (Bh + Bl): 2 MMAs per (mt,nt) -> 32 MMAs/kt-warp (was 48).
// A staged in smem, single plane, pitch 264 halves (conflict-free frags).
// MODE 0: LN+GELU -> fp32 x. MODE 1: LN+GELU -> fp16 plane. MODE 2: +bias -> fp32.
// ---------------------------------------------------------------------------
#define APITCH 264                          // halves; 132 uint32 words per row
#define ASMEM_ELEMS (64 * APITCH)
#define ASMEM_BYTES (ASMEM_ELEMS * 2)       // 33792 B

#define MMA_F16(c, a, b0, b1)                                                         \
    asm volatile(                                                                     \
        "mma.sync.aligned.m16n8k16.row.col.f32.f16.f16.f32 "                          \
        "{%0,%1,%2,%3}, {%4,%5,%6,%7}, {%8,%9}, {%0,%1,%2,%3};"                       \
        : "+f"(c[0]), "+f"(c[1]), "+f"(c[2]), "+f"(c[3])                              \
        : "r"(a[0]), "r"(a[1]), "r"(a[2]), "r"(a[3]), "r"(b0), "r"(b1))

template<int MODE>
__global__ void __launch_bounds__(256, 2)
hgemm_kernel(const __half* __restrict__ Ah, const uint4* __restrict__ Bp,
             const float* __restrict__ bias, const float* __restrict__ gamma,
             const float* __restrict__ beta, float* __restrict__ xout,
             __half* __restrict__ oh, float* __restrict__ fout, int n) {
    extern __shared__ __half sA[];               // single plane, pitch APITCH
    __shared__ float red[64][4][2];

    int tid = threadIdx.x, lane = tid & 31, w = tid >> 5;
    int wn = w & 3, wm = w >> 2;
    int t = lane & 3, g = lane >> 2;
    int m0 = blockIdx.x * 64;
    int rbase = m0 + wm * 32 + g;

    // ---- cooperative A-tile load, fully coalesced (2048 uint4) ----
#pragma unroll
    for (int i = 0; i < 8; i++) {
        int idx = tid + 256 * i;              // 0..2047
        int r = idx >> 5, q = idx & 31;       // row 0..63, uint4 index 0..31
        int gr = m0 + r;
        uint4 v = make_uint4(0u, 0u, 0u, 0u);
        if (gr < n) v = *reinterpret_cast<const uint4*>(Ah + (size_t)gr * D + q * 8);
        *reinterpret_cast<uint4*>(sA + r * APITCH + q * 8) = v;
    }
    __syncthreads();

    const uint32_t* sh32 = reinterpret_cast<const uint32_t*>(sA);
    int arow = wm * 32 + g;

    float acc[2][8][4];
#pragma unroll
    for (int mt = 0; mt < 2; mt++)
#pragma unroll
        for (int nt = 0; nt < 8; nt++)
#pragma unroll
            for (int c = 0; c < 4; c++) acc[mt][nt][c] = 0.f;

    const uint4* bwarp = Bp + (size_t)(wn * 8) * 32 + lane;

#pragma unroll
    for (int kt = 0; kt < 16; kt++) {
        int ko = kt * 8 + t;
        uint32_t ah[2][4];
#pragma unroll
        for (int mt = 0; mt < 2; mt++) {
            int r0 = (arow + mt * 16) * 132;
            int r1 = r0 + 8 * 132;
            ah[mt][0] = sh32[r0 + ko];
            ah[mt][1] = sh32[r1 + ko];
            ah[mt][2] = sh32[r0 + ko + 4];
            ah[mt][3] = sh32[r1 + ko + 4];
        }
        const uint4* bk = bwarp + (size_t)(kt * 32) * 32;
        uint4 bcur = __ldg(bk);
#pragma unroll
        for (int nt = 0; nt < 8; nt++) {
            uint4 bnext = (nt < 7) ? __ldg(bk + (size_t)(nt + 1) * 32) : bcur;
#pragma unroll
            for (int mt = 0; mt < 2; mt++) {
                MMA_F16(acc[mt][nt], ah[mt], bcur.x, bcur.y);   // A*Bh
                MMA_F16(acc[mt][nt], ah[mt], bcur.z, bcur.w);   // A*Bl
            }
            bcur = bnext;
        }
    }

    // ---- epilogue. cols for (nt): cb = wn*64 + nt*8 + 2t (pair cb, cb+1) ----
    if (MODE == 2) {
#pragma unroll
        for (int mt = 0; mt < 2; mt++)
#pragma unroll
            for (int half = 0; half < 2; half++) {
                int row = rbase + mt * 16 + half * 8;
                if (row >= n) continue;
#pragma unroll
                for (int nt = 0; nt < 8; nt++) {
                    int cb = wn * 64 + nt * 8 + 2 * t;
                    float2 bb = __ldg(reinterpret_cast<const float2*>(bias + cb));
                    float2 o;
                    o.x = acc[mt][nt][half * 2 + 0] + bb.x;
                    o.y = acc[mt][nt][half * 2 + 1] + bb.y;
                    *reinterpret_cast<float2*>(fout + (size_t)row * D + cb) = o;
                }
            }
        return;
    }

    float sm[4] = {0.f, 0.f, 0.f, 0.f}, sq[4] = {0.f, 0.f, 0.f, 0.f};
#pragma unroll
    for (int mt = 0; mt < 2; mt++)
#pragma unroll
        for (int nt = 0; nt < 8; nt++) {
            int cb = wn * 64 + nt * 8 + 2 * t;
            float2 bb = __ldg(reinterpret_cast<const float2*>(bias + cb));
            float v00 = acc[mt][nt][0] + bb.x, v01 = acc[mt][nt][1] + bb.y;
            float v10 = acc[mt][nt][2] + bb.x, v11 = acc[mt][nt][3] + bb.y;
            sm[mt * 2 + 0] += v00 + v01; sq[mt * 2 + 0] += v00 * v00 + v01 * v01;
            sm[mt * 2 + 1] += v10 + v11; sq[mt * 2 + 1] += v10 * v10 + v11 * v11;
        }
#pragma unroll
    for (int r = 0; r < 4; r++) {
#pragma unroll
        for (int o = 1; o < 4; o <<= 1) {
            sm[r] += __shfl_xor_sync(0xffffffffu, sm[r], o);
            sq[r] += __shfl_xor_sync(0xffffffffu, sq[r], o);
        }
    }
    if (t == 0) {
#pragma unroll
        for (int r = 0; r < 4; r++) {
            int lr = wm * 32 + (r >> 1) * 16 + (r & 1) * 8 + g;
            red[lr][wn][0] = sm[r];
            red[lr][wn][1] = sq[r];
        }
    }
    __syncthreads();
    float mean[4], rstd[4];
#pragma unroll
    for (int r = 0; r < 4; r++) {
        int lr = wm * 32 + (r >> 1) * 16 + (r & 1) * 8 + g;
        float S = 0.f, Q = 0.f;
#pragma unroll
        for (int j = 0; j < 4; j++) { S += red[lr][j][0]; Q += red[lr][j][1]; }
        float mu = S * (1.f / 256.f);
        mean[r] = mu;
        rstd[r] = rsqrtf(Q * (1.f / 256.f) - mu * mu + 1e-5f);
    }
#pragma unroll
    for (int mt = 0; mt < 2; mt++)
#pragma unroll
        for (int nt = 0; nt < 8; nt++) {
            int cb = wn * 64 + nt * 8 + 2 * t;
            float2 bb = __ldg(reinterpret_cast<const float2*>(bias + cb));
            float2 gg = __ldg(reinterpret_cast<const float2*>(gamma + cb));
            float2 be = __ldg(reinterpret_cast<const float2*>(beta + cb));
#pragma unroll
            for (int half = 0; half < 2; half++) {
                int row = rbase + mt * 16 + half * 8;
                if (row >= n) continue;
                int r = mt * 2 + half;
                float v0 = acc[mt][nt][half * 2 + 0] + bb.x;
                float v1 = acc[mt][nt][half * 2 + 1] + bb.y;
                float t0 = (v0 - mean[r]) * rstd[r] * gg.x + be.x;
                float t1 = (v1 - mean[r]) * rstd[r] * gg.y + be.y;
                float ge0 = 0.5f * t0 * (1.f + erff(t0 * 0.70710678118654752f));
                float ge1 = 0.5f * t1 * (1.f + erff(t1 * 0.70710678118654752f));
                if (MODE == 0) {
                    float2 o; o.x = ge0; o.y = ge1;
                    *reinterpret_cast<float2*>(xout + (size_t)row * D + cb) = o;
                } else {
                    *reinterpret_cast<uint32_t*>(oh + (size_t)row * D + cb) =
                        pkh(__float2half_rn(ge0), __float2half_rn(ge1));
                }
            }
        }
}

// ---------------------------------------------------------------------------
// launch (R6 serial structure — overlap attempts retired)
// ---------------------------------------------------------------------------
extern "C" void kernel_launch(void* const* d_in, const int* in_sizes, int n_in,
                              void* d_out, int out_size) {
    const float* node = (const float*)d_in[0];
    const int*   src  = (const int*)d_in[1];
    const int*   dst  = (const int*)d_in[2];
    const float* ew   = (const float*)d_in[3];
    const float* W1   = (const float*)d_in[4];
    const float* b1   = (const float*)d_in[5];
    const float* g1   = (const float*)d_in[6];
    const float* be1  = (const float*)d_in[7];
    const float* W2   = (const float*)d_in[8];
    const float* b2   = (const float*)d_in[9];
    const float* g2   = (const float*)d_in[10];
    const float* be2  = (const float*)d_in[11];
    const float* Wp   = (const float*)d_in[12];
    const float* bp   = (const float*)d_in[13];
    float* out = (float*)d_out;

    int n = in_sizes[0] / D;
    int nedges = in_sizes[1];

    __half *ah, *ch;
    float* x;
    int *cnt, *spill_cnt;
    int2* esw;
    int4* spill;
    uint4 *bp1, *bp2, *bp3;
    cudaGetSymbolAddress((void**)&ah, g_ah);
    cudaGetSymbolAddress((void**)&ch, g_ch);
    cudaGetSymbolAddress((void**)&x, g_x);
    cudaGetSymbolAddress((void**)&cnt, g_cnt);
    cudaGetSymbolAddress((void**)&esw, g_esw);
    cudaGetSymbolAddress((void**)&spill, g_spill);
    cudaGetSymbolAddress((void**)&spill_cnt, g_spill_cnt);
    cudaGetSymbolAddress((void**)&bp1, g_bp1);
    cudaGetSymbolAddress((void**)&bp2, g_bp2);
    cudaGetSymbolAddress((void**)&bp3, g_bp3);

    cudaFuncSetAttribute(hgemm_kernel<0>, cudaFuncAttributeMaxDynamicSharedMemorySize, ASMEM_BYTES);
    cudaFuncSetAttribute(hgemm_kernel<1>, cudaFuncAttributeMaxDynamicSharedMemorySize, ASMEM_BYTES);
    cudaFuncSetAttribute(hgemm_kernel<2>, cudaFuncAttributeMaxDynamicSharedMemorySize, ASMEM_BYTES);

    int edgeBlocks = (nedges + 255) / 256;
    int spmmBlocks = (n + 7) / 8;
    int gemmBlocks = (n + 63) / 64;
    dim3 prepGrid((16 * 32 * 32 + 255) / 256, 3);

    // ---- build + weight prep ----
    cudaMemsetAsync(cnt, 0, (size_t)n * sizeof(int));
    cudaMemsetAsync(spill_cnt, 0, sizeof(int));
    bucket_kernel<<<edgeBlocks, 256>>>(src, dst, ew, cnt, esw, spill, spill_cnt, nedges);
    prep_b_kernel<<<prepGrid, 256>>>(W1, W2, Wp, bp1, bp2, bp3);

    // ---- Layer 1: spmm(node) -> fp16 plane; gemm -> fp32 x ----
    spmm_kernel<<<spmmBlocks, 256>>>(node, esw, cnt, spill, spill_cnt, ah, n);
    hgemm_kernel<0><<<gemmBlocks, 256, ASMEM_BYTES>>>(ah, bp1, b1, g1, be1, x, nullptr, nullptr, n);

    // ---- Layer 2: spmm(x) -> fp16 plane; gemm -> fp16 plane ----
    spmm_kernel<<<spmmBlocks, 256>>>(x, esw, cnt, spill, spill_cnt, ah, n);
    hgemm_kernel<1><<<gemmBlocks, 256, ASMEM_BYTES>>>(ah, bp2, b2, g2, be2, nullptr, ch, nullptr, n);

    // ---- Projection: gemm(fp16 plane) -> fp32 out ----
    hgemm_kernel<2><<<gemmBlocks, 256, ASMEM_BYTES>>>(ch, bp3, bp, nullptr, nullptr, nullptr, nullptr, out, n);
}